// round 15
// baseline (speedup 1.0000x reference)
#include <cuda_runtime.h>
#include <cuda_fp16.h>
#include <cstdint>

// MOELinearB: out[e] = x[e] @ W[e]^T, E=8, N=4096, R=128, OUT=4096, fp32.
// R15: R14 (barrier-free tiles, fragment-packed W via LDG, permuted STG.128
// epilogue, persistent stealing) + race-free job handoff: ping-pong ctrl
// slots so a fast warp's next-job pop can never clobber the slot a slow warp
// still has to read (two-barrier separation).

#define E_   8
#define N_   4096
#define R_   128
#define OUT_ 4096

#define BM 128
#define BN 64
#define NTILE 8
#define THREADS 256
#define NCTA 296
#define NJOBS (E_ * (N_ / BM) * (OUT_ / (BN * NTILE)))   // 2048

#define XTOT (E_ * N_ * R_)
#define WTOT (E_ * OUT_ * R_)

// X scratch: row-major fp16. W scratch: fragment-packed (see below).
__device__ __half g_xh[XTOT];
// W fragments: entry fidx = ((e*512 + nb)*4 + ksp)*32 + lane, 16B each:
//   word0 = W[n][k0..k0+1], word1 = W[n][k0+8..9],
//   word2 = W[n][k0+16..17], word3 = W[n][k0+24..25]  (fp16x2 each)
// where n = (nb>>2)*32 + bperm((nb&3)*8 + lane/4), k0 = ksp*32 + (lane&3)*2.
__device__ uint4 g_wf[WTOT / 8];     // 8.39 MB
__device__ int   g_job_ctr;

#define RSTRIDE_B 272
#define A_REGION  (128 * RSTRIDE_B)             // 34816
#define OFF_CTRL  (2 * A_REGION)                // 69632
#define SMEM_BYTES (OFF_CTRL + 16)              // 69648 -> 2 CTAs/SM

// Output-column permutation (same function as R13's smem-slot permutation).
static __device__ __host__ __forceinline__ int bperm(int r) {
    return (r & 48) | ((r & 6) << 1) | ((r >> 2) & 2) | (r & 1);
}

// ---------------- Kernel 1: convert X (row-major) + pack W fragments ----------------
__global__ __launch_bounds__(256)
void convert_kernel(const float* __restrict__ X, const float* __restrict__ Wt)
{
    if (blockIdx.x == 0 && threadIdx.x == 0) g_job_ctr = NCTA;

    const int idx = blockIdx.x * blockDim.x + threadIdx.x;
    const int xq = XTOT / 4;

    if (idx < xq) {
        float4 v = reinterpret_cast<const float4*>(X)[idx];
        __half2 p0 = __floats2half2_rn(v.x, v.y);
        __half2 p1 = __floats2half2_rn(v.z, v.w);
        reinterpret_cast<uint2*>(g_xh)[idx] =
            make_uint2(*reinterpret_cast<uint32_t*>(&p0),
                       *reinterpret_cast<uint32_t*>(&p1));
        return;
    }

    const int widx = idx - xq;
    if (widx >= WTOT / 8) return;
    const int e   = widx >> 16;
    const int rem = widx & 65535;
    const int nb  = rem >> 7;
    const int ksp = (rem >> 5) & 3;
    const int l   = rem & 31;
    const int j   = l >> 2;
    const int q   = l & 3;
    const int n   = (nb >> 2) * 32 + bperm((nb & 3) * 8 + j);
    const int k0  = ksp * 32 + q * 2;

    const float* src = Wt + ((size_t)e * OUT_ + n) * R_ + k0;
    float2 a = *reinterpret_cast<const float2*>(src);
    float2 b = *reinterpret_cast<const float2*>(src + 8);
    float2 c = *reinterpret_cast<const float2*>(src + 16);
    float2 d = *reinterpret_cast<const float2*>(src + 24);
    __half2 ha = __floats2half2_rn(a.x, a.y);
    __half2 hb = __floats2half2_rn(b.x, b.y);
    __half2 hc = __floats2half2_rn(c.x, c.y);
    __half2 hd = __floats2half2_rn(d.x, d.y);
    g_wf[widx] = make_uint4(*reinterpret_cast<uint32_t*>(&ha),
                            *reinterpret_cast<uint32_t*>(&hb),
                            *reinterpret_cast<uint32_t*>(&hc),
                            *reinterpret_cast<uint32_t*>(&hd));
}

// ---------------- Kernel 2: GEMM ----------------
static __device__ __forceinline__ void mma_f16(float* d, const uint32_t* a,
                                               const uint32_t* b) {
    asm volatile(
        "mma.sync.aligned.m16n8k16.row.col.f32.f16.f16.f32 "
        "{%0,%1,%2,%3}, {%4,%5,%6,%7}, {%8,%9}, {%0,%1,%2,%3};"
        : "+f"(d[0]), "+f"(d[1]), "+f"(d[2]), "+f"(d[3])
        : "r"(a[0]), "r"(a[1]), "r"(a[2]), "r"(a[3]), "r"(b[0]), "r"(b[1]));
}

static __device__ __forceinline__ void ldsm4(uint32_t* r, uint32_t addr) {
    asm volatile("ldmatrix.sync.aligned.m8n8.x4.shared.b16 {%0,%1,%2,%3}, [%4];"
                 : "=r"(r[0]), "=r"(r[1]), "=r"(r[2]), "=r"(r[3]) : "r"(addr));
}

static __device__ __forceinline__ void cp16(uint32_t dst, const void* src) {
    asm volatile("cp.async.cg.shared.global [%0], [%1], 16;"
                 :: "r"(dst), "l"(src) : "memory");
}

static __device__ __forceinline__ uint32_t smem_u32(const void* p) {
    uint32_t a;
    asm("{ .reg .u64 t; cvta.to.shared.u64 t, %1; cvt.u32.u64 %0, t; }"
        : "=r"(a) : "l"(p));
    return a;
}

static __device__ __forceinline__ void decode_job(int j, int& e, int& bm, int& bn0)
{
    e   = j >> 8;
    int rem = j & 255;
    bm  = (rem >> 3) << 7;
    bn0 = (rem & 7) << 9;
}

__global__ __launch_bounds__(THREADS, 2)
void moe_f16_mma_kernel(float* __restrict__ O)
{
    extern __shared__ char smem[];
    const uint32_t sbase = smem_u32(smem);
    volatile int* ctrl = reinterpret_cast<volatile int*>(smem + OFF_CTRL);

    const int tid  = threadIdx.x;
    const int wid  = tid >> 5;
    const int lane = tid & 31;
    const int grp  = lane >> 2;
    const int qc   = lane & 3;
    const int wm   = wid >> 1;   // 0..3 -> M offset wm*32
    const int wn   = wid & 1;    // 0..1 -> N offset wn*32

    const uint32_t a_loff = (uint32_t)((wm * 32 + (lane & 15)) * RSTRIDE_B
                                       + (lane >> 4) * 16);

    auto stageA = [&](int abuf, const __half* Ap) {
        const uint32_t sb = sbase + (uint32_t)(abuf * A_REGION);
#pragma unroll
        for (int it = 0; it < 8; it++) {
            const int idx = tid + it * THREADS;
            const int row = idx >> 4;
            const int c   = idx & 15;
            cp16(sb + (uint32_t)(row * RSTRIDE_B + c * 16), Ap + row * R_ + c * 8);
        }
        asm volatile("cp.async.commit_group;" ::: "memory");
    };

    int job  = blockIdx.x;
    int abuf = 0;
    int par  = 0;

    // prologue: stage first job's A; pop first chain candidate into ctrl[0]
    {
        int e, bm, bn0; decode_job(job, e, bm, bn0);
        stageA(0, g_xh + (size_t)e * N_ * R_ + (size_t)bm * R_);
        if (tid == 0) ctrl[0] = atomicAdd(&g_job_ctr, 1);
    }

    while (job < NJOBS) {
        int e, bm, bn0; decode_job(job, e, bm, bn0);
        float* C = O + (size_t)e * N_ * OUT_;

        asm volatile("cp.async.wait_group 0;" ::: "memory");
        __syncthreads();                 // A(job) + ctrl[par] visible

        // Read chain target IMMEDIATELY (register). ctrl[par] is only
        // rewritten by tid0 after the NEXT head barrier -> race-free.
        const int nxt = ctrl[par];
        if (tid == 0) ctrl[par ^ 1] = atomicAdd(&g_job_ctr, 1);

        const uint32_t sA = sbase + (uint32_t)(abuf * A_REGION);

#pragma unroll 1
        for (int t = 0; t < NTILE; t++) {
            if (t == 5 && nxt < NJOBS) {
                int e2, bm2, bn2; decode_job(nxt, e2, bm2, bn2);
                stageA(abuf ^ 1, g_xh + (size_t)e2 * N_ * R_ + (size_t)bm2 * R_);
            }

            // B fragment base for this tile/warp
            const int nbb = ((bn0 >> 5) + t * 2 + wn) * 4;
            const uint4* wfp = g_wf + ((size_t)e * 512 + nbb) * 128 + lane;

            float acc[2][4][4];
#pragma unroll
            for (int mt = 0; mt < 2; mt++)
#pragma unroll
                for (int nt = 0; nt < 4; nt++)
#pragma unroll
                    for (int q = 0; q < 4; q++)
                        acc[mt][nt][q] = 0.0f;

            uint32_t af[2][16], bf[2][16];

            // prefetch ksp=0
#pragma unroll
            for (int nt = 0; nt < 4; nt++) {
                uint4 v = wfp[nt * 128];
                bf[0][nt * 4 + 0] = v.x; bf[0][nt * 4 + 1] = v.y;
                bf[0][nt * 4 + 2] = v.z; bf[0][nt * 4 + 3] = v.w;
            }
#pragma unroll
            for (int k2 = 0; k2 < 2; k2++)
#pragma unroll
                for (int mt = 0; mt < 2; mt++)
                    ldsm4(af[0] + k2 * 8 + mt * 4,
                          sA + a_loff + (uint32_t)(mt * 16 * RSTRIDE_B) + (uint32_t)(k2 * 32));

#pragma unroll
            for (int ksp = 0; ksp < 4; ksp++) {
                const int cur = ksp & 1;
                if (ksp + 1 < 4) {
                    const int nx = cur ^ 1;
#pragma unroll
                    for (int nt = 0; nt < 4; nt++) {
                        uint4 v = wfp[nt * 128 + (ksp + 1) * 32];
                        bf[nx][nt * 4 + 0] = v.x; bf[nx][nt * 4 + 1] = v.y;
                        bf[nx][nt * 4 + 2] = v.z; bf[nx][nt * 4 + 3] = v.w;
                    }
#pragma unroll
                    for (int k2 = 0; k2 < 2; k2++)
#pragma unroll
                        for (int mt = 0; mt < 2; mt++)
                            ldsm4(af[nx] + k2 * 8 + mt * 4,
                                  sA + a_loff + (uint32_t)(mt * 16 * RSTRIDE_B)
                                     + (uint32_t)(((ksp + 1) * 2 + k2) * 32));
                }
#pragma unroll
                for (int k2 = 0; k2 < 2; k2++)
#pragma unroll
                    for (int mt = 0; mt < 2; mt++)
#pragma unroll
                        for (int nt = 0; nt < 4; nt++)
                            mma_f16(acc[mt][nt], af[cur] + k2 * 8 + mt * 4,
                                    bf[cur] + nt * 4 + k2 * 2);
            }

            // ---- epilogue: permuted layout -> 8x STG.128 per thread ----
            const int colb = bn0 + t * BN;
#pragma unroll
            for (int mt = 0; mt < 2; mt++) {
#pragma unroll
                for (int p = 0; p < 2; p++) {
                    const int row = bm + wm * 32 + mt * 16 + grp;
                    const int col = colb + wn * 32 + p * 16 + qc * 4;
                    float4 v0 = make_float4(acc[mt][2 * p][0], acc[mt][2 * p][1],
                                            acc[mt][2 * p + 1][0], acc[mt][2 * p + 1][1]);
                    float4 v1 = make_float4(acc[mt][2 * p][2], acc[mt][2 * p][3],
                                            acc[mt][2 * p + 1][2], acc[mt][2 * p + 1][3]);
                    __stcs(reinterpret_cast<float4*>(C + (size_t)row * OUT_ + col), v0);
                    __stcs(reinterpret_cast<float4*>(C + (size_t)(row + 8) * OUT_ + col), v1);
                }
            }
        }

        job = nxt;
        abuf ^= 1;
        par ^= 1;
    }
}

extern "C" void kernel_launch(void* const* d_in, const int* in_sizes, int n_in,
                              void* d_out, int out_size)
{
    const float* x = (const float*)d_in[0];   // [E, N, R]
    const float* w = (const float*)d_in[1];   // [E, OUT, R]
    float* out = (float*)d_out;               // [E, N, OUT]

    const int ncvt = XTOT / 4 + WTOT / 8;     // 1572864 threads
    convert_kernel<<<(ncvt + 255) / 256, 256>>>(x, w);

    cudaFuncSetAttribute(moe_f16_mma_kernel,
                         cudaFuncAttributeMaxDynamicSharedMemorySize, SMEM_BYTES);
    moe_f16_mma_kernel<<<NCTA, THREADS, SMEM_BYTES>>>(out);
}